// round 5
// baseline (speedup 1.0000x reference)
#include <cuda_runtime.h>
#include <cuda_bf16.h>
#include <cstdint>

// PatchMerging fused as split-bf16 mma.sync GEMM:
//   out[m,o] = rstd_m * dot(y_m, Wg[o,:]) + (bias_o - rstd_m*mu_m*s_o)
// Both operands split hi+lo in bf16; acc = hiA*hiB + hiA*loB + loA*hiB (fp32 accum).

#define M_TOTAL 65536
#define KDIM    768
#define NDIM    192
#define CH      96
#define BM      128
#define TB      256
#define NCHUNK  24       // K chunks of 32 floats
#define APITCH  20       // A row pitch in uint32 (16 data + 4 pad) -> conflict-free frags

// ---- device scratch ----
// Per chunk: 6144 uint32 = [hi: 3072][lo: 3072], fragment order for m16n8k16.row.col:
//   within half: ((nt*2 + ks)*64 + lane*2 + reg), uint32 packs bf16 pair (k, k+1)
//   k = chunk*32 + ks*16 + reg*8 + (lane&3)*2, n = nt*8 + (lane>>2)
__device__ uint32_t g_WgF2[NCHUNK * 6144];
__device__ float g_s[NDIM];
__device__ float g_bias[NDIM];

#define MMA_BF16(d, a, b0, b1)                                               \
    asm volatile("mma.sync.aligned.m16n8k16.row.col.f32.bf16.bf16.f32 "      \
                 "{%0,%1,%2,%3}, {%4,%5,%6,%7}, {%8,%9}, {%0,%1,%2,%3};"     \
                 : "+f"((d)[0]), "+f"((d)[1]), "+f"((d)[2]), "+f"((d)[3])    \
                 : "r"((a)[0]), "r"((a)[1]), "r"((a)[2]), "r"((a)[3]),       \
                   "r"(b0), "r"(b1))

__device__ __forceinline__ void cp_async16(uint32_t dst, const void* src) {
    asm volatile("cp.async.cg.shared.global [%0], [%1], 16;" :: "r"(dst), "l"(src));
}
__device__ __forceinline__ uint32_t pack_bf16(__nv_bfloat16 a, __nv_bfloat16 b) {
    return (uint32_t)__bfloat16_as_ushort(a) | ((uint32_t)__bfloat16_as_ushort(b) << 16);
}

// ---- single merged prep kernel (so ncu -s5 lands on pm_main) ----
#define NFRAG (NCHUNK * 6144)
__global__ void pm_prep(const float* __restrict__ ln_w, const float* __restrict__ ln_b,
                        const float* __restrict__ W) {
    int bid = blockIdx.x;
    if (bid * 256 < NFRAG) {
        int idx = bid * 256 + threadIdx.x;
        if (idx < NFRAG) {
            int chunk = idx / 6144, rem = idx % 6144;
            int half = rem / 3072, rem2 = rem % 3072;
            int nt = rem2 >> 7, ks = (rem2 >> 6) & 1;
            int lane = (rem2 & 63) >> 1, reg = rem2 & 1;
            int k0 = chunk * 32 + ks * 16 + reg * 8 + (lane & 3) * 2;
            int n = nt * 8 + (lane >> 2);
            float w0 = ln_w[k0] * W[n * KDIM + k0];
            float w1 = ln_w[k0 + 1] * W[n * KDIM + k0 + 1];
            __nv_bfloat16 h0 = __float2bfloat16_rn(w0);
            __nv_bfloat16 h1 = __float2bfloat16_rn(w1);
            if (half == 0) {
                g_WgF2[idx] = pack_bf16(h0, h1);
            } else {
                __nv_bfloat16 l0 = __float2bfloat16_rn(w0 - __bfloat162float(h0));
                __nv_bfloat16 l1 = __float2bfloat16_rn(w1 - __bfloat162float(h1));
                g_WgF2[idx] = pack_bf16(l0, l1);
            }
        }
    } else {
        // last block: fold constants
        int o = threadIdx.x;
        if (o < NDIM) {
            float s = 0.f, b = 0.f;
            const float* wr = W + o * KDIM;
            for (int c = 0; c < KDIM; ++c) {
                float w = wr[c];
                s = fmaf(ln_w[c], w, s);
                b = fmaf(ln_b[c], w, b);
            }
            g_s[o] = s;
            g_bias[o] = b;
        }
    }
}

// ---- smem uint32-index layout ----
#define SA0      0          // Ahi[128*20]=2560, Alo +2560 -> 5120 per buffer
#define SA1      5120
#define SB0      10240      // 6144 per buffer (hi 3072 | lo 3072)
#define SB1      16384
#define SM_PSUM  22528
#define SM_PSQ   22784
#define SM_RSTD  23040
#define SM_RMU   23168
#define SM_SFOLD 23296
#define SM_BFOLD 23488
#define SM_WORDS 23680      // 94720 bytes

__global__ __launch_bounds__(TB, 1) void pm_main(const float* __restrict__ x,
                                                 float* __restrict__ out) {
    extern __shared__ uint32_t sm[];
    uint32_t* As[2] = {sm + SA0, sm + SA1};
    uint32_t* Bs[2] = {sm + SB0, sm + SB1};
    float* smf = (float*)sm;

    const int tid = threadIdx.x, lane = tid & 31, wid = tid >> 5;
    const int mw = wid >> 1, nw = wid & 1;
    const int bm = blockIdx.x;

    // A-gather geometry: 2 threads per row, 16 floats each
    const int r = tid >> 1, h = tid & 1;
    const int m = bm * BM + r;
    const int ww = m & 31, hh = (m >> 5) & 31, dd = (m >> 10) & 31, bb = m >> 15;
    const float* xbase = x + ((((long)bb * 64 + 2 * dd) * 64 + 2 * hh) * 64 + 2 * ww) * CH + h * 16;

    float acc[2][12][4];
#pragma unroll
    for (int i = 0; i < 2; ++i)
#pragma unroll
        for (int j = 0; j < 12; ++j)
#pragma unroll
            for (int u = 0; u < 4; ++u) acc[i][j][u] = 0.f;

    float psum = 0.f, psq = 0.f;
    float4 av[4];

    auto ldg_chunk = [&](int ch) {
        int seg = ch / 3, sub = ch - seg * 3;
        const float* p = xbase + ((seg >> 2) & 1) * 393216 + ((seg >> 1) & 1) * 6144 +
                         (seg & 1) * 96 + sub * 32;
#pragma unroll
        for (int v = 0; v < 4; ++v) av[v] = *(const float4*)(p + v * 4);
    };
    auto sts_chunk = [&](uint32_t* Ad) {
        uint32_t hi[8], lo[8];
#pragma unroll
        for (int v = 0; v < 4; ++v) {
            float4 t4 = av[v];
            psum += t4.x + t4.y + t4.z + t4.w;
            psq = fmaf(t4.x, t4.x, psq);
            psq = fmaf(t4.y, t4.y, psq);
            psq = fmaf(t4.z, t4.z, psq);
            psq = fmaf(t4.w, t4.w, psq);
            float f[4] = {t4.x, t4.y, t4.z, t4.w};
#pragma unroll
            for (int u = 0; u < 2; ++u) {
                float a = f[u * 2], b = f[u * 2 + 1];
                __nv_bfloat16 ha = __float2bfloat16_rn(a);
                __nv_bfloat16 hb = __float2bfloat16_rn(b);
                __nv_bfloat16 la = __float2bfloat16_rn(a - __bfloat162float(ha));
                __nv_bfloat16 lb = __float2bfloat16_rn(b - __bfloat162float(hb));
                hi[v * 2 + u] = pack_bf16(ha, hb);
                lo[v * 2 + u] = pack_bf16(la, lb);
            }
        }
        uint32_t base = r * APITCH + h * 8;
        *(uint4*)(Ad + base)            = *(uint4*)(hi);
        *(uint4*)(Ad + base + 4)        = *(uint4*)(hi + 4);
        *(uint4*)(Ad + 2560 + base)     = *(uint4*)(lo);
        *(uint4*)(Ad + 2560 + base + 4) = *(uint4*)(lo + 4);
    };
    auto cpB = [&](int ch, uint32_t* Bd) {
        const uint4* src = (const uint4*)(g_WgF2 + ch * 6144);
        uint32_t dst = (uint32_t)__cvta_generic_to_shared(Bd);
#pragma unroll
        for (int i = 0; i < 6; ++i) {
            int idx = tid + i * TB;
            cp_async16(dst + idx * 16, src + idx);
        }
    };
    auto compute = [&](const uint32_t* Ad, const uint32_t* Bd) {
#pragma unroll
        for (int ks = 0; ks < 2; ++ks) {
            uint32_t ahi[2][4], alo[2][4];
#pragma unroll
            for (int tmi = 0; tmi < 2; ++tmi) {
                int rb = mw * 32 + tmi * 16 + (lane >> 2);
                int j0 = ks * 8 + (lane & 3);
                ahi[tmi][0] = Ad[rb * APITCH + j0];
                ahi[tmi][1] = Ad[(rb + 8) * APITCH + j0];
                ahi[tmi][2] = Ad[rb * APITCH + j0 + 4];
                ahi[tmi][3] = Ad[(rb + 8) * APITCH + j0 + 4];
                alo[tmi][0] = Ad[2560 + rb * APITCH + j0];
                alo[tmi][1] = Ad[2560 + (rb + 8) * APITCH + j0];
                alo[tmi][2] = Ad[2560 + rb * APITCH + j0 + 4];
                alo[tmi][3] = Ad[2560 + (rb + 8) * APITCH + j0 + 4];
            }
#pragma unroll
            for (int nt = 0; nt < 12; ++nt) {
                int off = (((nw * 12 + nt) * 2 + ks) * 64 + lane * 2);
                uint2 bh = *(const uint2*)(Bd + off);
                uint2 bl = *(const uint2*)(Bd + 3072 + off);
#pragma unroll
                for (int tmi = 0; tmi < 2; ++tmi) {
                    MMA_BF16(acc[tmi][nt], ahi[tmi], bh.x, bh.y);
                    MMA_BF16(acc[tmi][nt], ahi[tmi], bl.x, bl.y);
                    MMA_BF16(acc[tmi][nt], alo[tmi], bh.x, bh.y);
                }
            }
        }
    };

    // prologue
    ldg_chunk(0);
    cpB(0, Bs[0]);
    sts_chunk(As[0]);
    asm volatile("cp.async.commit_group;" ::: "memory");
    asm volatile("cp.async.wait_group 0;" ::: "memory");
    __syncthreads();

    int cur = 0;
    for (int c = 0; c < NCHUNK; ++c) {
        const bool more = (c + 1 < NCHUNK);
        if (more) {
            ldg_chunk(c + 1);
            cpB(c + 1, Bs[cur ^ 1]);
            asm volatile("cp.async.commit_group;" ::: "memory");
        }
        compute(As[cur], Bs[cur]);
        if (more) {
            sts_chunk(As[cur ^ 1]);
            asm volatile("cp.async.wait_group 0;" ::: "memory");
        }
        __syncthreads();
        cur ^= 1;
    }

    // ---- LN stats reduce + fold constants ----
    smf[SM_PSUM + tid] = psum;
    smf[SM_PSQ + tid] = psq;
    if (tid < NDIM) {
        smf[SM_SFOLD + tid] = g_s[tid];
        smf[SM_BFOLD + tid] = g_bias[tid];
    }
    __syncthreads();
    if (tid < BM) {
        float su = smf[SM_PSUM + 2 * tid] + smf[SM_PSUM + 2 * tid + 1];
        float sq = smf[SM_PSQ + 2 * tid] + smf[SM_PSQ + 2 * tid + 1];
        float mu = su * (1.f / 768.f);
        float var = sq * (1.f / 768.f) - mu * mu;
        float rs = rsqrtf(var + 1e-5f);
        smf[SM_RSTD + tid] = rs;
        smf[SM_RMU + tid] = rs * mu;
    }
    __syncthreads();

    // ---- epilogue: LN fold + store (D layout of m16n8 frags) ----
#pragma unroll
    for (int tmi = 0; tmi < 2; ++tmi) {
        const int rbase = mw * 32 + tmi * 16 + (lane >> 2);
#pragma unroll
        for (int half = 0; half < 2; ++half) {
            const int rr = rbase + half * 8;
            const float rs = smf[SM_RSTD + rr];
            const float rm = smf[SM_RMU + rr];
            float* op = out + (size_t)(bm * BM + rr) * NDIM;
#pragma unroll
            for (int nt = 0; nt < 12; ++nt) {
                const int n0 = nw * 96 + nt * 8 + (lane & 3) * 2;
                float2 v;
                v.x = fmaf(rs, acc[tmi][nt][half * 2 + 0], smf[SM_BFOLD + n0] - rm * smf[SM_SFOLD + n0]);
                v.y = fmaf(rs, acc[tmi][nt][half * 2 + 1], smf[SM_BFOLD + n0 + 1] - rm * smf[SM_SFOLD + n0 + 1]);
                *(float2*)(op + n0) = v;
            }
        }
    }
}

extern "C" void kernel_launch(void* const* d_in, const int* in_sizes, int n_in,
                              void* d_out, int out_size) {
    const float* x    = (const float*)d_in[0];   // [2,64,64,64,96]
    const float* ln_w = (const float*)d_in[1];   // [768]
    const float* ln_b = (const float*)d_in[2];   // [768]
    const float* W    = (const float*)d_in[3];   // [192,768]
    float* out = (float*)d_out;                  // [65536,192]
    (void)in_sizes; (void)n_in; (void)out_size;

    cudaFuncSetAttribute(pm_main, cudaFuncAttributeMaxDynamicSharedMemorySize,
                         SM_WORDS * 4);

    pm_prep<<<(NFRAG + 255) / 256 + 1, 256>>>(ln_w, ln_b, W);
    pm_main<<<M_TOTAL / BM, TB, SM_WORDS * 4>>>(x, out);
}

// round 6
// speedup vs baseline: 1.5286x; 1.5286x over previous
#include <cuda_runtime.h>
#include <cuda_fp16.h>
#include <cstdint>

// PatchMerging fused as fp16 mma.sync GEMM (fp32 accumulate):
//   out[m,o] = rstd_m * dot(y_m, Wg[o,:]) + (bias_o - rstd_m*mu_m*s_o)
// fp16 (10 mantissa bits) == tf32 precision; proven 2.9e-4 rel_err in round 4.

#define M_TOTAL 65536
#define KDIM    768
#define NDIM    192
#define CH      96
#define BM      128
#define TB      512
#define NCHUNK  24       // K chunks of 32 floats
#define APITCH  20       // A row pitch in uint32 (16 data + 4 pad) -> conflict-free frags

// ---- device scratch ----
// B fragment-major fp16, per chunk 3072 uint32:
//   idx = chunk*3072 + ((nt*2 + ks)*64 + lane*2 + reg)
//   k = chunk*32 + ks*16 + reg*8 + (lane&3)*2 (pair), n = nt*8 + (lane>>2)
__device__ uint32_t g_WgH[NCHUNK * 3072];
__device__ float g_s[NDIM];
__device__ float g_bias[NDIM];

#define MMA_FP16(d, a, b0, b1)                                               \
    asm volatile("mma.sync.aligned.m16n8k16.row.col.f32.f16.f16.f32 "        \
                 "{%0,%1,%2,%3}, {%4,%5,%6,%7}, {%8,%9}, {%0,%1,%2,%3};"     \
                 : "+f"((d)[0]), "+f"((d)[1]), "+f"((d)[2]), "+f"((d)[3])    \
                 : "r"((a)[0]), "r"((a)[1]), "r"((a)[2]), "r"((a)[3]),       \
                   "r"(b0), "r"(b1))

__device__ __forceinline__ void cp_async16(uint32_t dst, const void* src) {
    asm volatile("cp.async.cg.shared.global [%0], [%1], 16;" :: "r"(dst), "l"(src));
}
__device__ __forceinline__ uint32_t pack_h2(float a, float b) {
    __half2 h = __floats2half2_rn(a, b);
    return *(uint32_t*)&h;
}

// ---- single merged prep kernel ----
#define NFRAG (NCHUNK * 3072)
__global__ void pm_prep(const float* __restrict__ ln_w, const float* __restrict__ ln_b,
                        const float* __restrict__ W) {
    int bid = blockIdx.x;
    if (bid * 256 < NFRAG) {
        int idx = bid * 256 + threadIdx.x;
        if (idx < NFRAG) {
            int chunk = idx / 3072, rem = idx % 3072;
            int nt = rem >> 7, w = rem & 127;
            int ks = w >> 6, lane = (w & 63) >> 1, reg = w & 1;
            int k0 = chunk * 32 + ks * 16 + reg * 8 + (lane & 3) * 2;
            int n = nt * 8 + (lane >> 2);
            g_WgH[idx] = pack_h2(ln_w[k0] * W[n * KDIM + k0],
                                 ln_w[k0 + 1] * W[n * KDIM + k0 + 1]);
        }
    } else {
        int o = threadIdx.x;
        if (o < NDIM) {
            float s = 0.f, b = 0.f;
            const float* wr = W + o * KDIM;
            for (int c = 0; c < KDIM; ++c) {
                float w = wr[c];
                s = fmaf(ln_w[c], w, s);
                b = fmaf(ln_b[c], w, b);
            }
            g_s[o] = s;
            g_bias[o] = b;
        }
    }
}

// ---- smem uint32-index layout ----
#define SA0      0          // 128*20 = 2560 words per buffer
#define SA1      2560
#define SB0      5120       // 3072 words per buffer
#define SB1      8192
#define SM_PSUM  11264      // 512
#define SM_PSQ   11776      // 512
#define SM_RSTD  12288      // 128
#define SM_RMU   12416      // 128
#define SM_SFOLD 12544      // 192
#define SM_BFOLD 12736      // 192
#define SM_WORDS 12928      // 51712 bytes

__global__ __launch_bounds__(TB, 1) void pm_main(const float* __restrict__ x,
                                                 float* __restrict__ out) {
    extern __shared__ uint32_t sm[];
    uint32_t* As[2] = {sm + SA0, sm + SA1};
    uint32_t* Bs[2] = {sm + SB0, sm + SB1};
    float* smf = (float*)sm;

    const int tid = threadIdx.x, lane = tid & 31, wid = tid >> 5;
    const int mw = wid >> 2, nw = wid & 3;       // 4x4 warp grid: warptile 32(M) x 48(N)
    const int bm = blockIdx.x;

    // A-gather geometry: 4 threads per row, 8 floats each
    const int r = tid >> 2, h = tid & 3;
    const int m = bm * BM + r;
    const int ww = m & 31, hh = (m >> 5) & 31, dd = (m >> 10) & 31, bb = m >> 15;
    const float* xbase = x + ((((long)bb * 64 + 2 * dd) * 64 + 2 * hh) * 64 + 2 * ww) * CH + h * 8;

    float acc[2][6][4];
#pragma unroll
    for (int i = 0; i < 2; ++i)
#pragma unroll
        for (int j = 0; j < 6; ++j)
#pragma unroll
            for (int u = 0; u < 4; ++u) acc[i][j][u] = 0.f;

    float psum = 0.f, psq = 0.f;
    float4 av[2];

    auto ldg_chunk = [&](int ch) {
        int seg = ch / 3, sub = ch - seg * 3;
        const float* p = xbase + ((seg >> 2) & 1) * 393216 + ((seg >> 1) & 1) * 6144 +
                         (seg & 1) * 96 + sub * 32;
        av[0] = *(const float4*)(p);
        av[1] = *(const float4*)(p + 4);
    };
    auto sts_chunk = [&](uint32_t* Ad) {
        uint32_t pk[4];
#pragma unroll
        for (int v = 0; v < 2; ++v) {
            float4 t4 = av[v];
            psum += t4.x + t4.y + t4.z + t4.w;
            psq = fmaf(t4.x, t4.x, psq);
            psq = fmaf(t4.y, t4.y, psq);
            psq = fmaf(t4.z, t4.z, psq);
            psq = fmaf(t4.w, t4.w, psq);
            pk[v * 2]     = pack_h2(t4.x, t4.y);
            pk[v * 2 + 1] = pack_h2(t4.z, t4.w);
        }
        *(uint4*)(Ad + r * APITCH + h * 4) = *(uint4*)pk;
    };
    auto cpB = [&](int ch, uint32_t* Bd) {
        const uint4* src = (const uint4*)(g_WgH + ch * 3072);
        uint32_t dst = (uint32_t)__cvta_generic_to_shared(Bd);
        cp_async16(dst + tid * 16, src + tid);
        if (tid < 256) cp_async16(dst + (tid + 512) * 16, src + tid + 512);
    };
    auto compute = [&](const uint32_t* Ad, const uint32_t* Bd) {
#pragma unroll
        for (int ks = 0; ks < 2; ++ks) {
            uint32_t a[2][4];
#pragma unroll
            for (int tmi = 0; tmi < 2; ++tmi) {
                int rb = mw * 32 + tmi * 16 + (lane >> 2);
                int j0 = ks * 8 + (lane & 3);
                a[tmi][0] = Ad[rb * APITCH + j0];
                a[tmi][1] = Ad[(rb + 8) * APITCH + j0];
                a[tmi][2] = Ad[rb * APITCH + j0 + 4];
                a[tmi][3] = Ad[(rb + 8) * APITCH + j0 + 4];
            }
#pragma unroll
            for (int nt = 0; nt < 6; ++nt) {
                uint2 b = *(const uint2*)(Bd + (((nw * 6 + nt) * 2 + ks) * 64 + lane * 2));
                MMA_FP16(acc[0][nt], a[0], b.x, b.y);
                MMA_FP16(acc[1][nt], a[1], b.x, b.y);
            }
        }
    };

    // prologue
    ldg_chunk(0);
    cpB(0, Bs[0]);
    sts_chunk(As[0]);
    asm volatile("cp.async.commit_group;" ::: "memory");
    asm volatile("cp.async.wait_group 0;" ::: "memory");
    __syncthreads();

    int cur = 0;
    for (int c = 0; c < NCHUNK; ++c) {
        const bool more = (c + 1 < NCHUNK);
        if (more) {
            ldg_chunk(c + 1);
            cpB(c + 1, Bs[cur ^ 1]);
            asm volatile("cp.async.commit_group;" ::: "memory");
        }
        compute(As[cur], Bs[cur]);
        if (more) {
            sts_chunk(As[cur ^ 1]);
            asm volatile("cp.async.wait_group 0;" ::: "memory");
        }
        __syncthreads();
        cur ^= 1;
    }

    // ---- LN stats reduce + fold constants ----
    smf[SM_PSUM + tid] = psum;
    smf[SM_PSQ + tid] = psq;
    if (tid < NDIM) {
        smf[SM_SFOLD + tid] = g_s[tid];
        smf[SM_BFOLD + tid] = g_bias[tid];
    }
    __syncthreads();
    if (tid < BM) {
        float su = smf[SM_PSUM + 4 * tid] + smf[SM_PSUM + 4 * tid + 1] +
                   smf[SM_PSUM + 4 * tid + 2] + smf[SM_PSUM + 4 * tid + 3];
        float sq = smf[SM_PSQ + 4 * tid] + smf[SM_PSQ + 4 * tid + 1] +
                   smf[SM_PSQ + 4 * tid + 2] + smf[SM_PSQ + 4 * tid + 3];
        float mu = su * (1.f / 768.f);
        float var = sq * (1.f / 768.f) - mu * mu;
        float rs = rsqrtf(var + 1e-5f);
        smf[SM_RSTD + tid] = rs;
        smf[SM_RMU + tid] = rs * mu;
    }
    __syncthreads();

    // ---- epilogue: LN fold + store ----
#pragma unroll
    for (int tmi = 0; tmi < 2; ++tmi) {
        const int rbase = mw * 32 + tmi * 16 + (lane >> 2);
#pragma unroll
        for (int half = 0; half < 2; ++half) {
            const int rr = rbase + half * 8;
            const float rs = smf[SM_RSTD + rr];
            const float rm = smf[SM_RMU + rr];
            float* op = out + (size_t)(bm * BM + rr) * NDIM;
#pragma unroll
            for (int nt = 0; nt < 6; ++nt) {
                const int n0 = nw * 48 + nt * 8 + (lane & 3) * 2;
                float2 v;
                v.x = fmaf(rs, acc[tmi][nt][half * 2 + 0], smf[SM_BFOLD + n0] - rm * smf[SM_SFOLD + n0]);
                v.y = fmaf(rs, acc[tmi][nt][half * 2 + 1], smf[SM_BFOLD + n0 + 1] - rm * smf[SM_SFOLD + n0 + 1]);
                *(float2*)(op + n0) = v;
            }
        }
    }
}

extern "C" void kernel_launch(void* const* d_in, const int* in_sizes, int n_in,
                              void* d_out, int out_size) {
    const float* x    = (const float*)d_in[0];   // [2,64,64,64,96]
    const float* ln_w = (const float*)d_in[1];   // [768]
    const float* ln_b = (const float*)d_in[2];   // [768]
    const float* W    = (const float*)d_in[3];   // [192,768]
    float* out = (float*)d_out;                  // [65536,192]
    (void)in_sizes; (void)n_in; (void)out_size;

    cudaFuncSetAttribute(pm_main, cudaFuncAttributeMaxDynamicSharedMemorySize,
                         SM_WORDS * 4);

    pm_prep<<<NFRAG / 256 + 1, 256>>>(ln_w, ln_b, W);
    pm_main<<<M_TOTAL / BM, TB, SM_WORDS * 4>>>(x, out);
}

// round 7
// speedup vs baseline: 2.3410x; 1.5315x over previous
#include <cuda_runtime.h>
#include <cuda_fp16.h>
#include <cstdint>

// PatchMerging fused as fp16 mma.sync GEMM (fp32 accumulate):
//   out[m,o] = rstd_m * dot(y_m, Wg[o,:]) + (bias_o - rstd_m*mu_m*s_o)
// R7: BM=64/TB=256 (2 CTAs/SM), ldmatrix A-fragments, fast warp-reduced prep.

#define M_TOTAL 65536
#define KDIM    768
#define NDIM    192
#define CH      96
#define BM      64
#define TB      256
#define NCHUNK  24       // K chunks of 32 floats
#define APITCH  20       // A row pitch in uint32 (16 data + 4 pad)

// ---- device scratch ----
// B fragment-major fp16, per chunk 3072 uint32:
//   idx = chunk*3072 + ((nt*2 + ks)*64 + lane*2 + reg)
__device__ uint32_t g_WgH[NCHUNK * 3072];
__device__ float g_s[NDIM];
__device__ float g_bias[NDIM];

#define MMA_FP16(d, a, b0, b1)                                               \
    asm volatile("mma.sync.aligned.m16n8k16.row.col.f32.f16.f16.f32 "        \
                 "{%0,%1,%2,%3}, {%4,%5,%6,%7}, {%8,%9}, {%0,%1,%2,%3};"     \
                 : "+f"((d)[0]), "+f"((d)[1]), "+f"((d)[2]), "+f"((d)[3])    \
                 : "r"((a)[0]), "r"((a)[1]), "r"((a)[2]), "r"((a)[3]),       \
                   "r"(b0), "r"(b1))

__device__ __forceinline__ void cp_async16(uint32_t dst, const void* src) {
    asm volatile("cp.async.cg.shared.global [%0], [%1], 16;" :: "r"(dst), "l"(src));
}
__device__ __forceinline__ uint32_t pack_h2(float a, float b) {
    __half2 h = __floats2half2_rn(a, b);
    return *(uint32_t*)&h;
}

// ---- prep: frag blocks + warp-per-output fold blocks ----
#define NFRAG (NCHUNK * 3072)
#define FRAG_BLOCKS (NFRAG / 256)          // 288
#define COL_BLOCKS  (NDIM / 8)             // 24 blocks x 8 warps = 192 warps
__global__ void pm_prep(const float* __restrict__ ln_w, const float* __restrict__ ln_b,
                        const float* __restrict__ W) {
    int bid = blockIdx.x;
    if (bid < FRAG_BLOCKS) {
        int idx = bid * 256 + threadIdx.x;
        int chunk = idx / 3072, rem = idx % 3072;
        int nt = rem >> 7, w = rem & 127;
        int ks = w >> 6, lane = (w & 63) >> 1, reg = w & 1;
        int k0 = chunk * 32 + ks * 16 + reg * 8 + (lane & 3) * 2;
        int n = nt * 8 + (lane >> 2);
        g_WgH[idx] = pack_h2(ln_w[k0] * W[n * KDIM + k0],
                             ln_w[k0 + 1] * W[n * KDIM + k0 + 1]);
    } else {
        // one warp per output column o: coalesced reduction over K
        int wlocal = threadIdx.x >> 5, lane = threadIdx.x & 31;
        int o = (bid - FRAG_BLOCKS) * 8 + wlocal;
        const float* wr = W + o * KDIM;
        float s = 0.f, b = 0.f;
#pragma unroll
        for (int i = 0; i < KDIM / 32; ++i) {
            int c = lane + i * 32;
            float w = wr[c];
            s = fmaf(ln_w[c], w, s);
            b = fmaf(ln_b[c], w, b);
        }
#pragma unroll
        for (int d = 16; d > 0; d >>= 1) {
            s += __shfl_xor_sync(0xffffffffu, s, d);
            b += __shfl_xor_sync(0xffffffffu, b, d);
        }
        if (lane == 0) {
            g_s[o] = s;
            g_bias[o] = b;
        }
    }
}

// ---- smem uint32-index layout ----
#define SA0      0          // 64*20 = 1280 words per buffer
#define SA1      1280
#define SB0      2560       // 3072 words per buffer
#define SB1      5632
#define SM_PSUM  8704       // 256
#define SM_PSQ   8960       // 256
#define SM_RSTD  9216       // 64
#define SM_RMU   9280       // 64
#define SM_SFOLD 9344       // 192
#define SM_BFOLD 9536       // 192
#define SM_WORDS 9728       // 38912 bytes -> 2 CTAs/SM fine

__global__ __launch_bounds__(TB, 2) void pm_main(const float* __restrict__ x,
                                                 float* __restrict__ out) {
    extern __shared__ uint32_t sm[];
    uint32_t* As[2] = {sm + SA0, sm + SA1};
    uint32_t* Bs[2] = {sm + SB0, sm + SB1};
    float* smf = (float*)sm;

    const int tid = threadIdx.x, lane = tid & 31, wid = tid >> 5;
    const int mw = wid >> 2, nw = wid & 3;       // 2x4 warp grid: warptile 32(M) x 48(N)
    const int bm = blockIdx.x;

    // A-gather geometry: 4 threads per row, 8 floats each
    const int r = tid >> 2, h = tid & 3;
    const int m = bm * BM + r;
    const int ww = m & 31, hh = (m >> 5) & 31, dd = (m >> 10) & 31, bb = m >> 15;
    const float* xbase = x + ((((long)bb * 64 + 2 * dd) * 64 + 2 * hh) * 64 + 2 * ww) * CH + h * 8;

    float acc[2][6][4];
#pragma unroll
    for (int i = 0; i < 2; ++i)
#pragma unroll
        for (int j = 0; j < 6; ++j)
#pragma unroll
            for (int u = 0; u < 4; ++u) acc[i][j][u] = 0.f;

    float psum = 0.f, psq = 0.f;
    float4 av[2];

    auto ldg_chunk = [&](int ch) {
        int seg = ch / 3, sub = ch - seg * 3;
        const float* p = xbase + ((seg >> 2) & 1) * 393216 + ((seg >> 1) & 1) * 6144 +
                         (seg & 1) * 96 + sub * 32;
        av[0] = *(const float4*)(p);
        av[1] = *(const float4*)(p + 4);
    };
    auto sts_chunk = [&](uint32_t* Ad) {
        uint32_t pk[4];
#pragma unroll
        for (int v = 0; v < 2; ++v) {
            float4 t4 = av[v];
            psum += t4.x + t4.y + t4.z + t4.w;
            psq = fmaf(t4.x, t4.x, psq);
            psq = fmaf(t4.y, t4.y, psq);
            psq = fmaf(t4.z, t4.z, psq);
            psq = fmaf(t4.w, t4.w, psq);
            pk[v * 2]     = pack_h2(t4.x, t4.y);
            pk[v * 2 + 1] = pack_h2(t4.z, t4.w);
        }
        *(uint4*)(Ad + r * APITCH + h * 4) = *(uint4*)pk;
    };
    auto cpB = [&](int ch, uint32_t* Bd) {
        const uint4* src = (const uint4*)(g_WgH + ch * 3072);
        uint32_t dst = (uint32_t)__cvta_generic_to_shared(Bd);
#pragma unroll
        for (int i = 0; i < 3; ++i)
            cp_async16(dst + (tid + i * TB) * 16, src + tid + i * TB);
    };
    auto compute = [&](const uint32_t* Ad, const uint32_t* Bd) {
#pragma unroll
        for (int ks = 0; ks < 2; ++ks) {
            uint32_t a[2][4];
#pragma unroll
            for (int tmi = 0; tmi < 2; ++tmi) {
                // ldmatrix x4: lanes 0-15 -> rows 0-15 (k lo 8), 16-31 -> rows 0-15 (k hi 8)
                int row = mw * 32 + tmi * 16 + (lane & 15);
                const uint32_t* ap = Ad + row * APITCH + ks * 8 + (lane >> 4) * 4;
                uint32_t sa = (uint32_t)__cvta_generic_to_shared(ap);
                asm volatile("ldmatrix.sync.aligned.m8n8.x4.shared.b16 {%0,%1,%2,%3}, [%4];"
                             : "=r"(a[tmi][0]), "=r"(a[tmi][1]), "=r"(a[tmi][2]), "=r"(a[tmi][3])
                             : "r"(sa));
            }
#pragma unroll
            for (int nt = 0; nt < 6; ++nt) {
                uint2 b = *(const uint2*)(Bd + (((nw * 6 + nt) * 2 + ks) * 64 + lane * 2));
                MMA_FP16(acc[0][nt], a[0], b.x, b.y);
                MMA_FP16(acc[1][nt], a[1], b.x, b.y);
            }
        }
    };

    // prologue
    ldg_chunk(0);
    cpB(0, Bs[0]);
    sts_chunk(As[0]);
    asm volatile("cp.async.commit_group;" ::: "memory");
    asm volatile("cp.async.wait_group 0;" ::: "memory");
    __syncthreads();

    int cur = 0;
    for (int c = 0; c < NCHUNK; ++c) {
        const bool more = (c + 1 < NCHUNK);
        if (more) {
            ldg_chunk(c + 1);
            cpB(c + 1, Bs[cur ^ 1]);
            asm volatile("cp.async.commit_group;" ::: "memory");
        }
        compute(As[cur], Bs[cur]);
        if (more) {
            sts_chunk(As[cur ^ 1]);
            asm volatile("cp.async.wait_group 0;" ::: "memory");
        }
        __syncthreads();
        cur ^= 1;
    }

    // ---- LN stats reduce + fold constants ----
    smf[SM_PSUM + tid] = psum;
    smf[SM_PSQ + tid] = psq;
    if (tid < NDIM) {
        smf[SM_SFOLD + tid] = g_s[tid];
        smf[SM_BFOLD + tid] = g_bias[tid];
    }
    __syncthreads();
    if (tid < BM) {
        float su = smf[SM_PSUM + 4 * tid] + smf[SM_PSUM + 4 * tid + 1] +
                   smf[SM_PSUM + 4 * tid + 2] + smf[SM_PSUM + 4 * tid + 3];
        float sq = smf[SM_PSQ + 4 * tid] + smf[SM_PSQ + 4 * tid + 1] +
                   smf[SM_PSQ + 4 * tid + 2] + smf[SM_PSQ + 4 * tid + 3];
        float mu = su * (1.f / 768.f);
        float var = sq * (1.f / 768.f) - mu * mu;
        float rs = rsqrtf(var + 1e-5f);
        smf[SM_RSTD + tid] = rs;
        smf[SM_RMU + tid] = rs * mu;
    }
    __syncthreads();

    // ---- epilogue: LN fold + store ----
#pragma unroll
    for (int tmi = 0; tmi < 2; ++tmi) {
        const int rbase = mw * 32 + tmi * 16 + (lane >> 2);
#pragma unroll
        for (int half = 0; half < 2; ++half) {
            const int rr = rbase + half * 8;
            const float rs = smf[SM_RSTD + rr];
            const float rm = smf[SM_RMU + rr];
            float* op = out + (size_t)(bm * BM + rr) * NDIM;
#pragma unroll
            for (int nt = 0; nt < 6; ++nt) {
                const int n0 = nw * 48 + nt * 8 + (lane & 3) * 2;
                float2 v;
                v.x = fmaf(rs, acc[tmi][nt][half * 2 + 0], smf[SM_BFOLD + n0] - rm * smf[SM_SFOLD + n0]);
                v.y = fmaf(rs, acc[tmi][nt][half * 2 + 1], smf[SM_BFOLD + n0 + 1] - rm * smf[SM_SFOLD + n0 + 1]);
                *(float2*)(op + n0) = v;
            }
        }
    }
}

extern "C" void kernel_launch(void* const* d_in, const int* in_sizes, int n_in,
                              void* d_out, int out_size) {
    const float* x    = (const float*)d_in[0];   // [2,64,64,64,96]
    const float* ln_w = (const float*)d_in[1];   // [768]
    const float* ln_b = (const float*)d_in[2];   // [768]
    const float* W    = (const float*)d_in[3];   // [192,768]
    float* out = (float*)d_out;                  // [65536,192]
    (void)in_sizes; (void)n_in; (void)out_size;

    cudaFuncSetAttribute(pm_main, cudaFuncAttributeMaxDynamicSharedMemorySize,
                         SM_WORDS * 4);

    pm_prep<<<FRAG_BLOCKS + COL_BLOCKS, 256>>>(ln_w, ln_b, W);
    pm_main<<<M_TOTAL / BM, TB, SM_WORDS * 4>>>(x, out);
}

// round 8
// speedup vs baseline: 2.7576x; 1.1779x over previous
#include <cuda_runtime.h>
#include <cuda_fp16.h>
#include <cstdint>

// PatchMerging fused as fp16 mma.sync GEMM (fp32 accumulate):
//   out[m,o] = rstd_m * dot(y_m, Wg[o,:]) + (bias_o - rstd_m*mu_m*s_o)
// R8: K-chunk = 96 (full segment) -> 8 syncs instead of 24; tensor-dominant iterations.

#define M_TOTAL 65536
#define KDIM    768
#define NDIM    192
#define CH      96
#define BM      64
#define TB      256
#define NCHUNK  8        // K chunks of 96 floats (one patch segment each)
#define APITCH  52       // A row pitch in uint32 (48 data + 4 pad; 13x16B, coprime w/ 8)

// ---- device scratch ----
// B fragment-major fp16, per chunk 9216 uint32:
//   idx = chunk*9216 + ((nt*6 + ks)*64 + lane*2 + reg), nt 0..23, ks 0..5
//   k0 = chunk*96 + ks*16 + reg*8 + (lane&3)*2 (pair), n = nt*8 + (lane>>2)
__device__ uint32_t g_WgH[NCHUNK * 9216];
__device__ float g_s[NDIM];
__device__ float g_bias[NDIM];

#define MMA_FP16(d, a, b0, b1)                                               \
    asm volatile("mma.sync.aligned.m16n8k16.row.col.f32.f16.f16.f32 "        \
                 "{%0,%1,%2,%3}, {%4,%5,%6,%7}, {%8,%9}, {%0,%1,%2,%3};"     \
                 : "+f"((d)[0]), "+f"((d)[1]), "+f"((d)[2]), "+f"((d)[3])    \
                 : "r"((a)[0]), "r"((a)[1]), "r"((a)[2]), "r"((a)[3]),       \
                   "r"(b0), "r"(b1))

__device__ __forceinline__ void cp_async16(uint32_t dst, const void* src) {
    asm volatile("cp.async.cg.shared.global [%0], [%1], 16;" :: "r"(dst), "l"(src));
}
__device__ __forceinline__ uint32_t pack_h2(float a, float b) {
    __half2 h = __floats2half2_rn(a, b);
    return *(uint32_t*)&h;
}

// ---- prep: frag blocks + warp-per-output fold blocks ----
#define NFRAG (NCHUNK * 9216)
#define FRAG_BLOCKS (NFRAG / 256)          // 288
#define COL_BLOCKS  (NDIM / 8)             // 24 blocks x 8 warps
__global__ void pm_prep(const float* __restrict__ ln_w, const float* __restrict__ ln_b,
                        const float* __restrict__ W) {
    int bid = blockIdx.x;
    if (bid < FRAG_BLOCKS) {
        int idx = bid * 256 + threadIdx.x;
        int chunk = idx / 9216, rem = idx % 9216;
        int nt = rem / 384, r2 = rem % 384;
        int ks = r2 >> 6, w = r2 & 63;
        int lane = w >> 1, reg = w & 1;
        int k0 = chunk * 96 + ks * 16 + reg * 8 + (lane & 3) * 2;
        int n = nt * 8 + (lane >> 2);
        g_WgH[idx] = pack_h2(ln_w[k0] * W[n * KDIM + k0],
                             ln_w[k0 + 1] * W[n * KDIM + k0 + 1]);
    } else {
        int wlocal = threadIdx.x >> 5, lane = threadIdx.x & 31;
        int o = (bid - FRAG_BLOCKS) * 8 + wlocal;
        const float* wr = W + o * KDIM;
        float s = 0.f, b = 0.f;
#pragma unroll
        for (int i = 0; i < KDIM / 32; ++i) {
            int c = lane + i * 32;
            float w = wr[c];
            s = fmaf(ln_w[c], w, s);
            b = fmaf(ln_b[c], w, b);
        }
#pragma unroll
        for (int d = 16; d > 0; d >>= 1) {
            s += __shfl_xor_sync(0xffffffffu, s, d);
            b += __shfl_xor_sync(0xffffffffu, b, d);
        }
        if (lane == 0) {
            g_s[o] = s;
            g_bias[o] = b;
        }
    }
}

// ---- smem uint32-index layout ----
#define SA0      0          // 64*52 = 3328 words per buffer
#define SA1      3328
#define SB0      6656       // 9216 words per buffer
#define SB1      15872
#define SM_PSUM  25088      // 256
#define SM_PSQ   25344      // 256
#define SM_RSTD  25600      // 64
#define SM_RMU   25664      // 64
#define SM_SFOLD 25728      // 192
#define SM_BFOLD 25920      // 192
#define SM_WORDS 26112      // 104448 bytes -> 2 CTAs/SM = 209KB

__global__ __launch_bounds__(TB, 2) void pm_main(const float* __restrict__ x,
                                                 float* __restrict__ out) {
    extern __shared__ uint32_t sm[];
    uint32_t* As[2] = {sm + SA0, sm + SA1};
    uint32_t* Bs[2] = {sm + SB0, sm + SB1};
    float* smf = (float*)sm;

    const int tid = threadIdx.x, lane = tid & 31, wid = tid >> 5;
    const int mw = wid >> 2, nw = wid & 3;       // 2x4 warp grid: warptile 32(M) x 48(N)
    const int bm = blockIdx.x;

    // A-gather: 4 threads per row; per half-chunk each thread moves 12 floats
    const int r = tid >> 2, h = tid & 3;
    const int m = bm * BM + r;
    const int ww = m & 31, hh = (m >> 5) & 31, dd = (m >> 10) & 31, bb = m >> 15;
    const float* xbase = x + ((((long)bb * 64 + 2 * dd) * 64 + 2 * hh) * 64 + 2 * ww) * CH;

    float acc[2][6][4];
#pragma unroll
    for (int i = 0; i < 2; ++i)
#pragma unroll
        for (int j = 0; j < 6; ++j)
#pragma unroll
            for (int u = 0; u < 4; ++u) acc[i][j][u] = 0.f;

    float psum = 0.f, psq = 0.f;
    float4 av[3];

    auto ldg_half = [&](int ch, int half) {
        const float* p = xbase + ((ch >> 2) & 1) * 393216 + ((ch >> 1) & 1) * 6144 +
                         (ch & 1) * 96 + half * 48 + h * 12;
        av[0] = *(const float4*)(p);
        av[1] = *(const float4*)(p + 4);
        av[2] = *(const float4*)(p + 8);
    };
    auto sts_half = [&](uint32_t* Ad, int half) {
        uint32_t* dst = Ad + r * APITCH + half * 24 + h * 6;
#pragma unroll
        for (int v = 0; v < 3; ++v) {
            float4 t4 = av[v];
            psum += t4.x + t4.y + t4.z + t4.w;
            psq = fmaf(t4.x, t4.x, psq);
            psq = fmaf(t4.y, t4.y, psq);
            psq = fmaf(t4.z, t4.z, psq);
            psq = fmaf(t4.w, t4.w, psq);
            uint2 pk;
            pk.x = pack_h2(t4.x, t4.y);
            pk.y = pack_h2(t4.z, t4.w);
            *(uint2*)(dst + v * 2) = pk;
        }
    };
    auto cpB = [&](int ch, uint32_t* Bd) {
        const uint4* src = (const uint4*)(g_WgH + ch * 9216);
        uint32_t dst = (uint32_t)__cvta_generic_to_shared(Bd);
#pragma unroll
        for (int i = 0; i < 9; ++i)
            cp_async16(dst + (tid + i * TB) * 16, src + tid + i * TB);
    };
    auto compute_half = [&](const uint32_t* Ad, const uint32_t* Bd, int ks0) {
#pragma unroll
        for (int kk = 0; kk < 3; ++kk) {
            const int ks = ks0 + kk;
            uint32_t a[2][4];
#pragma unroll
            for (int tmi = 0; tmi < 2; ++tmi) {
                int row = mw * 32 + tmi * 16 + (lane & 15);
                const uint32_t* ap = Ad + row * APITCH + ks * 8 + (lane >> 4) * 4;
                uint32_t sa = (uint32_t)__cvta_generic_to_shared(ap);
                asm volatile("ldmatrix.sync.aligned.m8n8.x4.shared.b16 {%0,%1,%2,%3}, [%4];"
                             : "=r"(a[tmi][0]), "=r"(a[tmi][1]), "=r"(a[tmi][2]), "=r"(a[tmi][3])
                             : "r"(sa));
            }
#pragma unroll
            for (int nt = 0; nt < 6; ++nt) {
                uint2 b = *(const uint2*)(Bd + (((nw * 6 + nt) * 6 + ks) * 64 + lane * 2));
                MMA_FP16(acc[0][nt], a[0], b.x, b.y);
                MMA_FP16(acc[1][nt], a[1], b.x, b.y);
            }
        }
    };

    // prologue: chunk 0
    cpB(0, Bs[0]);
    ldg_half(0, 0); sts_half(As[0], 0);
    ldg_half(0, 1); sts_half(As[0], 1);
    asm volatile("cp.async.commit_group;" ::: "memory");
    asm volatile("cp.async.wait_group 0;" ::: "memory");
    __syncthreads();

    int cur = 0;
    for (int c = 0; c < NCHUNK; ++c) {
        const bool more = (c + 1 < NCHUNK);
        if (more) {
            cpB(c + 1, Bs[cur ^ 1]);
            asm volatile("cp.async.commit_group;" ::: "memory");
            ldg_half(c + 1, 0);
        }
        compute_half(As[cur], Bs[cur], 0);
        if (more) {
            sts_half(As[cur ^ 1], 0);
            ldg_half(c + 1, 1);
        }
        compute_half(As[cur], Bs[cur], 3);
        if (more) {
            sts_half(As[cur ^ 1], 1);
            asm volatile("cp.async.wait_group 0;" ::: "memory");
        }
        __syncthreads();
        cur ^= 1;
    }

    // ---- LN stats reduce + fold constants ----
    smf[SM_PSUM + tid] = psum;
    smf[SM_PSQ + tid] = psq;
    if (tid < NDIM) {
        smf[SM_SFOLD + tid] = g_s[tid];
        smf[SM_BFOLD + tid] = g_bias[tid];
    }
    __syncthreads();
    if (tid < BM) {
        float su = smf[SM_PSUM + 4 * tid] + smf[SM_PSUM + 4 * tid + 1] +
                   smf[SM_PSUM + 4 * tid + 2] + smf[SM_PSUM + 4 * tid + 3];
        float sq = smf[SM_PSQ + 4 * tid] + smf[SM_PSQ + 4 * tid + 1] +
                   smf[SM_PSQ + 4 * tid + 2] + smf[SM_PSQ + 4 * tid + 3];
        float mu = su * (1.f / 768.f);
        float var = sq * (1.f / 768.f) - mu * mu;
        float rs = rsqrtf(var + 1e-5f);
        smf[SM_RSTD + tid] = rs;
        smf[SM_RMU + tid] = rs * mu;
    }
    __syncthreads();

    // ---- epilogue: LN fold + store ----
#pragma unroll
    for (int tmi = 0; tmi < 2; ++tmi) {
        const int rbase = mw * 32 + tmi * 16 + (lane >> 2);
#pragma unroll
        for (int half = 0; half < 2; ++half) {
            const int rr = rbase + half * 8;
            const float rs = smf[SM_RSTD + rr];
            const float rm = smf[SM_RMU + rr];
            float* op = out + (size_t)(bm * BM + rr) * NDIM;
#pragma unroll
            for (int nt = 0; nt < 6; ++nt) {
                const int n0 = nw * 48 + nt * 8 + (lane & 3) * 2;
                float2 v;
                v.x = fmaf(rs, acc[tmi][nt][half * 2 + 0], smf[SM_BFOLD + n0] - rm * smf[SM_SFOLD + n0]);
                v.y = fmaf(rs, acc[tmi][nt][half * 2 + 1], smf[SM_BFOLD + n0 + 1] - rm * smf[SM_SFOLD + n0 + 1]);
                *(float2*)(op + n0) = v;
            }
        }
    }
}

extern "C" void kernel_launch(void* const* d_in, const int* in_sizes, int n_in,
                              void* d_out, int out_size) {
    const float* x    = (const float*)d_in[0];   // [2,64,64,64,96]
    const float* ln_w = (const float*)d_in[1];   // [768]
    const float* ln_b = (const float*)d_in[2];   // [768]
    const float* W    = (const float*)d_in[3];   // [192,768]
    float* out = (float*)d_out;                  // [65536,192]
    (void)in_sizes; (void)n_in; (void)out_size;

    cudaFuncSetAttribute(pm_main, cudaFuncAttributeMaxDynamicSharedMemorySize,
                         SM_WORDS * 4);

    pm_prep<<<FRAG_BLOCKS + COL_BLOCKS, 256>>>(ln_w, ln_b, W);
    pm_main<<<M_TOTAL / BM, TB, SM_WORDS * 4>>>(x, out);
}